// round 11
// baseline (speedup 1.0000x reference)
#include <cuda_runtime.h>
#include <cuda_bf16.h>
#include <cstdint>
#include <math.h>

#define B_  2048
#define N_  4096
#define E_  256
#define H_  4
#define TILE 64
#define THREADS 256
#define SF  72                       // floats per smem row: 8B lane accesses conflict-free per phase
#define NBLK 64                      // N_/64
#define NCTA (NBLK*(NBLK+1)/2)       // 2080 triangular tiles
#define NPERS 296                    // persistent CTAs = 2 * 148 (<= 2*152 on GB300)

// smem float-index layout for accumulators (base SM_ACC)
#define SRI  0                       // [64][4] row R
#define SCDI 256                     // [64]    row dot
#define SCNI 320                     // [64][4] row cnt
#define SRJ  576                     // [64][4] col R
#define SCDJ 832                     // [64]    col dot
#define SCNJ 896                     // [64][4] col cnt
#define ACC_FLOATS 1152

// smem byte layout
#define SM_BITS 0                    // 64*4 = 256
#define SM_ACC  256                  // 4608 bytes
#define SM_A0   5120
#define TILE_B  (64 * SF * 4)        // 18432
#define SM_B0   (SM_A0 + TILE_B)
#define SM_A1   (SM_B0 + TILE_B)
#define SM_B1   (SM_A1 + TILE_B)
#define SMEM_TOTAL (SM_B1 + TILE_B)  // 78848

#define BIAS 64.0f                   // folded into MMA accumulator; cancels at finalize

__device__ float    g_F[N_ * E_];    // normalized * sqrt(log2e/T), tf32-rounded, k-permuted
__device__ unsigned g_bits[B_];
__device__ float    g_R[N_ * H_];    // sum_{j!=i} exp(dot/T) * 2^64
__device__ float    g_cnt[N_ * H_];
__device__ float    g_dot[N_];       // sum mask * (dot*log2e/T + 64)
__device__ unsigned g_ctr[3];        // grid barrier counters (memset to 0 each call)
__device__ float    g_partial[2];    // final (sum, count)  (memset to 0 each call)

// ---------------- helpers ----------------
__device__ __forceinline__ float ex2f(float x) {
    float r; asm("ex2.approx.ftz.f32 %0, %1;" : "=f"(r) : "f"(x)); return r;
}
__device__ __forceinline__ float lg2f(float x) {
    float r; asm("lg2.approx.f32 %0, %1;" : "=f"(r) : "f"(x)); return r;
}
__device__ __forceinline__ void cpasync16(uint32_t dst, const float* src) {
    asm volatile("cp.async.cg.shared.global [%0], [%1], 16;" :: "r"(dst), "l"(src));
}
#define CP_COMMIT() asm volatile("cp.async.commit_group;" ::: "memory")
#define CP_WAIT(n)  asm volatile("cp.async.wait_group %0;" :: "n"(n) : "memory")

__device__ __forceinline__ void mma_tf32(float* c, const uint32_t* a, const uint32_t* b) {
    asm volatile(
        "mma.sync.aligned.m16n8k8.row.col.f32.tf32.tf32.f32 "
        "{%0,%1,%2,%3}, {%4,%5,%6,%7}, {%8,%9}, {%0,%1,%2,%3};\n"
        : "+f"(c[0]), "+f"(c[1]), "+f"(c[2]), "+f"(c[3])
        : "r"(a[0]), "r"(a[1]), "r"(a[2]), "r"(a[3]), "r"(b[0]), "r"(b[1]));
}

// stage one per-head [64][64] tile into a [64][SF] buffer (1024 16B chunks, 4/thread)
__device__ __forceinline__ void loadHead(uint32_t smdst, int g0, int h, int tid) {
#pragma unroll
    for (int t = 0; t < 4; ++t) {
        int idx = t * THREADS + tid;
        int r = idx >> 4, c4 = idx & 15;
        cpasync16(smdst + (uint32_t)(r * (SF * 4) + c4 * 16),
                  g_F + (g0 + r) * E_ + h * 64 + c4 * 4);
    }
}

// grid-wide barrier over NPERS co-resident CTAs
__device__ __forceinline__ void gridBar(int j) {
    __threadfence();
    __syncthreads();
    if (threadIdx.x == 0) {
        atomicAdd(&g_ctr[j], 1u);
        while (atomicAdd(&g_ctr[j], 0u) < (unsigned)NPERS) __nanosleep(64);
        __threadfence();
    }
    __syncthreads();
}

// ---------------- persistent kernel: pre -> tiles -> finalize ----------------
__global__ void __launch_bounds__(THREADS, 2) mainK(
    const float* __restrict__ feat, const float* __restrict__ labels,
    float* __restrict__ out)
{
    extern __shared__ char smem[];
    unsigned* sBits = (unsigned*)(smem + SM_BITS);
    float* sAcc = (float*)(smem + SM_ACC);
    const uint32_t smem_base = (uint32_t)__cvta_generic_to_shared(smem);
    const int tid = threadIdx.x;

    // ======== Phase 0: zero + bits + normalize/permute (float4) ========
    {
        int c4 = tid & 63;
        for (int i = blockIdx.x * 4 + (tid >> 6); i < N_; i += NPERS * 4) {
            int v = i >> 11, b = i & (B_ - 1);
            if (c4 < 4) { g_R[i * 4 + c4] = 0.f; g_cnt[i * 4 + c4] = 0.f; }
            else if (c4 == 4) g_dot[i] = 0.f;
            else if (c4 == 5 && i < B_) {
                unsigned m = 0;
#pragma unroll
                for (int k = 0; k < 10; ++k)
                    if (labels[i * 10 + k] > 0.5f) m |= (1u << k);
                g_bits[i] = m;
            }
            float4 val = *(const float4*)(feat + (b * 2 + v) * E_ + c4 * 4);
            float sq = val.x * val.x + val.y * val.y + val.z * val.z + val.w * val.w;
#pragma unroll
            for (int o = 1; o <= 8; o <<= 1) sq += __shfl_xor_sync(0xffffffffu, sq, o);
            float inv = 1.0f / fmaxf(sqrtf(sq), 1e-12f);
            const float SC = 4.53981654f;          // sqrt(log2e / 0.07)
            int h = c4 >> 4;
            float* dst = g_F + i * E_ + h * 64;
            float e4[4] = {val.x, val.y, val.z, val.w};
#pragma unroll
            for (int t = 0; t < 4; ++t) {
                int eloc = (c4 & 15) * 4 + t;
                int ks = eloc >> 3, c = eloc & 7;
                int newpos = ks * 8 + 2 * (c & 3) + (c >> 2);   // k-perm for LDS.64 frags
                float y = e4[t] * inv * SC;
                uint32_t t32;
                asm("cvt.rna.tf32.f32 %0, %1;" : "=r"(t32) : "f"(y));
                dst[newpos] = __uint_as_float(t32);
            }
        }
    }
    gridBar(0);

    // ======== Phase 1: triangular tile loop ========
    const int w   = tid >> 5;
    const int lid = tid & 31;
    const int wi  = w >> 2;            // 0..1 : rows 32*wi..
    const int wj  = w & 3;             // 0..3 : cols 16*wj..
    const int qt  = lid >> 2;          // 0..7
    const int m4  = lid & 3;           // 0..3

    for (int t = blockIdx.x; t < NCTA; t += NPERS) {
        int by = (int)((sqrtf(8.f * (float)t + 1.f) - 1.f) * 0.5f);
        while ((by + 1) * (by + 2) / 2 <= t) ++by;
        while (by * (by + 1) / 2 > t) --by;
        int bx = t - by * (by + 1) / 2;
        const int i0 = bx * TILE;
        const int j0 = by * TILE;
        const bool diag = (bx == by);

        loadHead(smem_base + SM_A0, i0, 0, tid);
        loadHead(smem_base + SM_B0, j0, 0, tid);
        CP_COMMIT();
        loadHead(smem_base + SM_A1, i0, 1, tid);
        loadHead(smem_base + SM_B1, j0, 1, tid);
        CP_COMMIT();

        if (tid < TILE) sBits[tid] = __ldcg(&g_bits[(j0 + tid) & (B_ - 1)]);
        for (int z = tid; z < ACC_FLOATS; z += THREADS) sAcc[z] = 0.f;

        unsigned bI[4];
#pragma unroll
        for (int r4 = 0; r4 < 4; ++r4) {
            int rl = 32 * wi + 16 * (r4 >> 1) + qt + 8 * (r4 & 1);
            bI[r4] = __ldcg(&g_bits[(i0 + rl) & (B_ - 1)]);
        }
        float R[4][4];
        unsigned bp[16];
#pragma unroll
        for (int r4 = 0; r4 < 4; ++r4)
#pragma unroll
            for (int h = 0; h < 4; ++h) R[r4][h] = 0.f;
#pragma unroll
        for (int p = 0; p < 16; ++p) bp[p] = 0u;

#pragma unroll
        for (int h = 0; h < 4; ++h) {
            if (h < 3) CP_WAIT(1); else CP_WAIT(0);
            __syncthreads();

            const uint32_t aOff = (h & 1) ? SM_A1 : SM_A0;
            const uint32_t bOff = (h & 1) ? SM_B1 : SM_B0;
            const uint32_t* aB = (const uint32_t*)(smem + aOff) + (32 * wi + qt) * SF + 2 * m4;
            const uint32_t* bB = (const uint32_t*)(smem + bOff) + (16 * wj + qt) * SF + 2 * m4;

            float C[2][2][4];
#pragma unroll
            for (int mt = 0; mt < 2; ++mt)
#pragma unroll
                for (int nt = 0; nt < 2; ++nt)
#pragma unroll
                    for (int k = 0; k < 4; ++k) C[mt][nt][k] = BIAS;

#pragma unroll
            for (int ks = 0; ks < 8; ++ks) {
                uint32_t a[2][4], b[2][2];
#pragma unroll
                for (int mt = 0; mt < 2; ++mt) {
                    uint2 lo = *(const uint2*)(aB + mt * (16 * SF) + ks * 8);
                    uint2 hi = *(const uint2*)(aB + mt * (16 * SF) + 8 * SF + ks * 8);
                    a[mt][0] = lo.x; a[mt][1] = hi.x; a[mt][2] = lo.y; a[mt][3] = hi.y;
                }
#pragma unroll
                for (int nt = 0; nt < 2; ++nt) {
                    uint2 bv = *(const uint2*)(bB + nt * (8 * SF) + ks * 8);
                    b[nt][0] = bv.x; b[nt][1] = bv.y;
                }
#pragma unroll
                for (int mt = 0; mt < 2; ++mt)
#pragma unroll
                    for (int nt = 0; nt < 2; ++nt)
                        mma_tf32(C[mt][nt], a[mt], b[nt]);
            }

            // per-head epilogue
            float RjA[4] = {0.f, 0.f, 0.f, 0.f};
#pragma unroll
            for (int mt = 0; mt < 2; ++mt)
#pragma unroll
                for (int nt = 0; nt < 2; ++nt)
#pragma unroll
                    for (int k = 0; k < 4; ++k) {
                        const int half = k >> 1, cbit = k & 1;
                        float d = C[mt][nt][k];          // dot*log2e/T + 64  (> 0)
                        float e = ex2f(d);               // exp(dot/T) * 2^64
                        if (diag) {
                            const int rl = 32 * wi + 16 * mt + qt + 8 * half;
                            const int cl = 16 * wj + 8 * nt + 2 * m4 + cbit;
                            if (rl == cl) e = 0.f;
                        }
                        R[mt * 2 + half][h] += e;
                        RjA[nt * 2 + cbit] += e;
                        const int bpi = (mt * 2 + half) * 4 + nt * 2 + cbit;
                        unsigned en = (__float_as_uint(d) & 0xFFFFFFFCu) | (unsigned)h;
                        bp[bpi] = bp[bpi] > en ? bp[bpi] : en;
                    }
            if (!diag) {
#pragma unroll
                for (int o = 4; o <= 16; o <<= 1)
#pragma unroll
                    for (int c = 0; c < 4; ++c)
                        RjA[c] += __shfl_xor_sync(0xffffffffu, RjA[c], o);
                if (qt == 0) {
#pragma unroll
                    for (int c = 0; c < 4; ++c) {
                        int cl = 16 * wj + 8 * (c >> 1) + 2 * m4 + (c & 1);
                        atomicAdd(&sAcc[SRJ + cl * 4 + h], RjA[c]);
                    }
                }
            }

            __syncthreads();
            if (h + 2 < 4) {
                loadHead(smem_base + ((h & 1) ? SM_A1 : SM_A0), i0, h + 2, tid);
                loadHead(smem_base + ((h & 1) ? SM_B1 : SM_B0), j0, h + 2, tid);
                CP_COMMIT();
            }
        }

        // ---- masked accumulation ----
        unsigned bJv[4];
#pragma unroll
        for (int c = 0; c < 4; ++c)
            bJv[c] = sBits[16 * wj + 8 * (c >> 1) + 2 * m4 + (c & 1)];

        float cdot[4]; unsigned cp_[4];
        float cdotj[4] = {0.f, 0.f, 0.f, 0.f};
        unsigned cpj[4] = {0u, 0u, 0u, 0u};

#pragma unroll
        for (int r4 = 0; r4 < 4; ++r4) {
            cdot[r4] = 0.f; cp_[r4] = 0u;
            const unsigned bIr = bI[r4];
            const int rl = 32 * wi + 16 * (r4 >> 1) + qt + 8 * (r4 & 1);
#pragma unroll
            for (int c = 0; c < 4; ++c) {
                bool m = ((bIr & bJv[c]) != 0u);
                if (diag) {
                    const int cl = 16 * wj + 8 * (c >> 1) + 2 * m4 + (c & 1);
                    if (rl == cl) m = false;
                }
                if (m) {
                    unsigned e = bp[r4 * 4 + c];
                    float dt = __uint_as_float(e & 0xFFFFFFFCu);   // biased dot
                    unsigned inc = 1u << ((e & 3u) * 8);
                    cdot[r4] += dt; cp_[r4] += inc;
                    cdotj[c] += dt; cpj[c]  += inc;
                }
            }
        }

#pragma unroll
        for (int o = 1; o <= 2; o <<= 1) {
#pragma unroll
            for (int r4 = 0; r4 < 4; ++r4) {
                cdot[r4] += __shfl_xor_sync(0xffffffffu, cdot[r4], o);
                cp_[r4]  += __shfl_xor_sync(0xffffffffu, cp_[r4], o);
#pragma unroll
                for (int h = 0; h < 4; ++h)
                    R[r4][h] += __shfl_xor_sync(0xffffffffu, R[r4][h], o);
            }
        }
        if (m4 == 0) {
#pragma unroll
            for (int r4 = 0; r4 < 4; ++r4) {
                const int rl = 32 * wi + 16 * (r4 >> 1) + qt + 8 * (r4 & 1);
                atomicAdd(&sAcc[SCDI + rl], cdot[r4]);
#pragma unroll
                for (int h = 0; h < 4; ++h) {
                    atomicAdd(&sAcc[SRI + rl * 4 + h], R[r4][h]);
                    float cn = (float)((cp_[r4] >> (8 * h)) & 255u);
                    if (cn != 0.f) atomicAdd(&sAcc[SCNI + rl * 4 + h], cn);
                }
            }
        }

        if (!diag) {
#pragma unroll
            for (int o = 4; o <= 16; o <<= 1)
#pragma unroll
                for (int c = 0; c < 4; ++c) {
                    cdotj[c] += __shfl_xor_sync(0xffffffffu, cdotj[c], o);
                    cpj[c]   += __shfl_xor_sync(0xffffffffu, cpj[c], o);
                }
            if (qt == 0) {
#pragma unroll
                for (int c = 0; c < 4; ++c) {
                    int cl = 16 * wj + 8 * (c >> 1) + 2 * m4 + (c & 1);
                    if (cpj[c] != 0u) {
                        atomicAdd(&sAcc[SCDJ + cl], cdotj[c]);
#pragma unroll
                        for (int h = 0; h < 4; ++h) {
                            float cn = (float)((cpj[c] >> (8 * h)) & 255u);
                            if (cn != 0.f) atomicAdd(&sAcc[SCNJ + cl * 4 + h], cn);
                        }
                    }
                }
            }
        }

        // ---- coalesced global flush ----
        __syncthreads();
        if (tid < TILE) {
            const int rl = tid, gi = i0 + rl;
            atomicAdd(&g_dot[gi], sAcc[SCDI + rl]);
#pragma unroll
            for (int h = 0; h < 4; ++h) {
                atomicAdd(&g_R[gi * 4 + h], sAcc[SRI + rl * 4 + h]);
                float cn = sAcc[SCNI + rl * 4 + h];
                if (cn != 0.f) atomicAdd(&g_cnt[gi * 4 + h], cn);
            }
        } else if (!diag && tid < 2 * TILE) {
            const int cl = tid - TILE, gj = j0 + cl;
            atomicAdd(&g_dot[gj], sAcc[SCDJ + cl]);
#pragma unroll
            for (int h = 0; h < 4; ++h) {
                atomicAdd(&g_R[gj * 4 + h], sAcc[SRJ + cl * 4 + h]);
                float cn = sAcc[SCNJ + cl * 4 + h];
                if (cn != 0.f) atomicAdd(&g_cnt[gj * 4 + h], cn);
            }
        }
        __syncthreads();   // protect sAcc/smem reuse in next tile
    }
    gridBar(1);

    // ======== Phase 2: finalize ========
    // sum_mask log_prob = ln2 * ( sum d_biased - sum_h cnt_h * lg2(R_raw_h) )  (64*ct cancels)
    {
        float s = 0.f, c = 0.f;
        for (int i = blockIdx.x * THREADS + tid; i < N_; i += NPERS * THREADS) {
            float ct = 0.f;
            float acc = __ldcg(&g_dot[i]);
#pragma unroll
            for (int h = 0; h < 4; ++h) {
                float cn = __ldcg(&g_cnt[i * 4 + h]);
                ct  += cn;
                acc -= cn * lg2f(__ldcg(&g_R[i * 4 + h]));
            }
            float loss = -0.6931471805599453f * acc / ct;   // NaN when ct==0
            if (isfinite(loss)) { s += loss; c += 1.f; }
        }
#pragma unroll
        for (int o = 16; o; o >>= 1) {
            s += __shfl_xor_sync(0xffffffffu, s, o);
            c += __shfl_xor_sync(0xffffffffu, c, o);
        }
        __shared__ float rs[8], rc[8];
        if (lid == 0) { rs[w] = s; rc[w] = c; }
        __syncthreads();
        if (tid == 0) {
            float ts = 0.f, tc = 0.f;
#pragma unroll
            for (int x = 0; x < 8; ++x) { ts += rs[x]; tc += rc[x]; }
            if (ts != 0.f || tc != 0.f) {
                atomicAdd(&g_partial[0], ts);
                atomicAdd(&g_partial[1], tc);
            }
        }
    }
    gridBar(2);
    if (blockIdx.x == 0 && tid == 0)
        out[0] = __ldcg(&g_partial[0]) / __ldcg(&g_partial[1]);
}

// ---------------- launch ----------------
extern "C" void kernel_launch(void* const* d_in, const int* in_sizes, int n_in,
                              void* d_out, int out_size) {
    const float* features = (const float*)d_in[0];
    const float* labels   = (const float*)d_in[1];
    float* out = (float*)d_out;

    cudaFuncSetAttribute(mainK, cudaFuncAttributeMaxDynamicSharedMemorySize, SMEM_TOTAL);

    void* ctrPtr = nullptr;  cudaGetSymbolAddress(&ctrPtr, g_ctr);
    void* parPtr = nullptr;  cudaGetSymbolAddress(&parPtr, g_partial);
    cudaMemsetAsync(ctrPtr, 0, 3 * sizeof(unsigned));
    cudaMemsetAsync(parPtr, 0, 2 * sizeof(float));

    mainK<<<NPERS, THREADS, SMEM_TOTAL>>>(features, labels, out);
}

// round 13
// speedup vs baseline: 1.3157x; 1.3157x over previous
#include <cuda_runtime.h>
#include <cuda_bf16.h>
#include <cstdint>
#include <math.h>

#define B_  2048
#define N_  4096
#define E_  256
#define H_  4
#define TILE 64
#define THREADS 256
#define SH  272                      // halves per smem row (256 + 16 pad): conflict-free 8B phases
#define NBLK 64                      // N_/64
#define NCTA (NBLK*(NBLK+1)/2)       // 2080 triangular tiles

// smem float-index layout for accumulators (base SM_ACC)
#define SRI  0                       // [64][4] row R
#define SCDI 256                     // [64]    row dot
#define SCNI 320                     // [64][4] row cnt
#define SRJ  576                     // [64][4] col R
#define SCDJ 832                     // [64]    col dot
#define SCNJ 896                     // [64][4] col cnt
#define ACC_FLOATS 1152

// smem byte layout
#define SM_BITS 0                    // 64*4 = 256
#define SM_ACC  256                  // 4608 bytes
#define SM_A    4864
#define TILE_BH (64 * SH * 2)        // 34816 bytes (full-K bf16 tile)
#define SM_B    (SM_A + TILE_BH)
#define SMEM_TOTAL (SM_B + TILE_BH)  // 74496  -> 2 CTAs/SM

#define BIAS 64.0f                   // folded into MMA accumulator; cancels at finalize

static __device__ __nv_bfloat16 g_F[N_ * E_];  // normalized * sqrt(log2e/T), bf16, k-permuted
static __device__ unsigned g_bits[B_];
static __device__ float    g_R[N_ * H_];       // sum_{j!=i} exp(dot/T) * 2^64
static __device__ float    g_cnt[N_ * H_];
static __device__ float    g_dot[N_];          // sum mask * (dot*log2e/T + 64)

// ---------------- helpers ----------------
__device__ __forceinline__ float ex2f(float x) {
    float r; asm("ex2.approx.ftz.f32 %0, %1;" : "=f"(r) : "f"(x)); return r;
}
__device__ __forceinline__ float lg2f(float x) {
    float r; asm("lg2.approx.f32 %0, %1;" : "=f"(r) : "f"(x)); return r;
}
__device__ __forceinline__ void cpasync16(uint32_t dst, const void* src) {
    asm volatile("cp.async.cg.shared.global [%0], [%1], 16;" :: "r"(dst), "l"(src));
}
#define CP_COMMIT() asm volatile("cp.async.commit_group;" ::: "memory")
#define CP_WAIT0()  asm volatile("cp.async.wait_group 0;" ::: "memory")

__device__ __forceinline__ void mma_bf16(float* c, const uint32_t* a, const uint32_t* b) {
    asm volatile(
        "mma.sync.aligned.m16n8k16.row.col.f32.bf16.bf16.f32 "
        "{%0,%1,%2,%3}, {%4,%5,%6,%7}, {%8,%9}, {%0,%1,%2,%3};\n"
        : "+f"(c[0]), "+f"(c[1]), "+f"(c[2]), "+f"(c[3])
        : "r"(a[0]), "r"(a[1]), "r"(a[2]), "r"(a[3]), "r"(b[0]), "r"(b[1]));
}

// ---------------- preprocessing: zero + bits + normalize/permute -> bf16 ----------------
__global__ void preK(const float* __restrict__ feat, const float* __restrict__ labels) {
    int tid = threadIdx.x;
    int i = blockIdx.x * 4 + (tid >> 6);   // 4 rows per block; i = v*B + b (view-major)
    int c4 = tid & 63;                     // 4-float chunk within row
    int v = i >> 11, b = i & (B_ - 1);

    if (c4 < 4) { g_R[i * 4 + c4] = 0.f; g_cnt[i * 4 + c4] = 0.f; }
    else if (c4 == 4) g_dot[i] = 0.f;
    else if (c4 == 5 && i < B_) {
        unsigned m = 0;
#pragma unroll
        for (int k = 0; k < 10; ++k)
            if (labels[i * 10 + k] > 0.5f) m |= (1u << k);
        g_bits[i] = m;
    }

    float4 val = *(const float4*)(feat + (b * 2 + v) * E_ + c4 * 4);
    float sq = val.x * val.x + val.y * val.y + val.z * val.z + val.w * val.w;
#pragma unroll
    for (int o = 1; o <= 8; o <<= 1) sq += __shfl_xor_sync(0xffffffffu, sq, o);  // 16 lanes = 1 head
    float inv = 1.0f / fmaxf(sqrtf(sq), 1e-12f);
    const float SC = 4.53981654f;          // sqrt(log2e / 0.07)
    int h = c4 >> 4;
    __nv_bfloat16* dst = g_F + i * E_ + h * 64;
    float e4[4] = {val.x, val.y, val.z, val.w};
#pragma unroll
    for (int t = 0; t < 4; ++t) {
        int eloc = (c4 & 15) * 4 + t;      // 0..63 within head
        int ks = eloc >> 4, c = eloc & 15;
        // m16n8k16 k-perm: [2m,2m+1,2m+8,2m+9] -> contiguous [4m..4m+3]
        int newpos = ks * 16 + 4 * ((c & 7) >> 1) + 2 * (c >> 3) + (c & 1);
        dst[newpos] = __float2bfloat16(e4[t] * inv * SC);
    }
}

// ---------------- main: bf16 m16n8k16, triangular grid, single-shot tiles ----------------
__global__ void __launch_bounds__(THREADS, 2) mainK() {
    extern __shared__ char smem[];
    unsigned* sBits = (unsigned*)(smem + SM_BITS);
    float* sAcc = (float*)(smem + SM_ACC);
    const char* aT = smem + SM_A;
    const char* bT = smem + SM_B;
    const uint32_t smem_base = (uint32_t)__cvta_generic_to_shared(smem);

    const int tid = threadIdx.x;
    const int w   = tid >> 5;
    const int lid = tid & 31;
    const int wi  = w >> 2;            // 0..1 : rows 32*wi..
    const int wj  = w & 3;             // 0..3 : cols 16*wj..
    const int qt  = lid >> 2;          // 0..7
    const int m4  = lid & 3;           // 0..3

    // triangular decode: bx <= by
    int idx = blockIdx.x;
    int by = (int)((sqrtf(8.f * (float)idx + 1.f) - 1.f) * 0.5f);
    while ((by + 1) * (by + 2) / 2 <= idx) ++by;
    while (by * (by + 1) / 2 > idx) --by;
    int bx = idx - by * (by + 1) / 2;
    const int i0 = bx * TILE;
    const int j0 = by * TILE;
    const bool diag = (bx == by);

    // ---- stage full-K A and B tiles (bf16), one group ----
#pragma unroll
    for (int t = 0; t < 8; ++t) {      // A: 2048 16B chunks
        int x = t * THREADS + tid;
        int r = x >> 5, c = x & 31;    // 32 chunks (512B) per row
        cpasync16(smem_base + SM_A + (uint32_t)(r * (SH * 2) + c * 16),
                  g_F + (i0 + r) * E_ + c * 8);
    }
#pragma unroll
    for (int t = 0; t < 8; ++t) {      // B
        int x = t * THREADS + tid;
        int r = x >> 5, c = x & 31;
        cpasync16(smem_base + SM_B + (uint32_t)(r * (SH * 2) + c * 16),
                  g_F + (j0 + r) * E_ + c * 8);
    }
    CP_COMMIT();

    if (tid < TILE) sBits[tid] = g_bits[(j0 + tid) & (B_ - 1)];
    for (int z = tid; z < ACC_FLOATS; z += THREADS) sAcc[z] = 0.f;

    unsigned bI[4];
#pragma unroll
    for (int r4 = 0; r4 < 4; ++r4) {
        int rl = 32 * wi + 16 * (r4 >> 1) + qt + 8 * (r4 & 1);
        bI[r4] = g_bits[(i0 + rl) & (B_ - 1)];
    }
    float R[4][4];
    unsigned bp[16];
#pragma unroll
    for (int r4 = 0; r4 < 4; ++r4)
#pragma unroll
        for (int h = 0; h < 4; ++h) R[r4][h] = 0.f;
#pragma unroll
    for (int p = 0; p < 16; ++p) bp[p] = 0u;

    CP_WAIT0();
    __syncthreads();

#pragma unroll
    for (int h = 0; h < 4; ++h) {
        float C[2][2][4];
#pragma unroll
        for (int mt = 0; mt < 2; ++mt)
#pragma unroll
            for (int nt = 0; nt < 2; ++nt)
#pragma unroll
                for (int k = 0; k < 4; ++k) C[mt][nt][k] = BIAS;

#pragma unroll
        for (int ks = 0; ks < 4; ++ks) {
            const uint32_t koff = (uint32_t)(h * 128 + ks * 32 + m4 * 8);
            uint32_t a[2][4], b[2][2];
#pragma unroll
            for (int mt = 0; mt < 2; ++mt) {
                int r = 32 * wi + 16 * mt + qt;
                uint2 lo = *(const uint2*)(aT + r * (SH * 2) + koff);
                uint2 hi = *(const uint2*)(aT + (r + 8) * (SH * 2) + koff);
                a[mt][0] = lo.x; a[mt][1] = hi.x; a[mt][2] = lo.y; a[mt][3] = hi.y;
            }
#pragma unroll
            for (int nt = 0; nt < 2; ++nt) {
                int r = 16 * wj + 8 * nt + qt;
                uint2 bv = *(const uint2*)(bT + r * (SH * 2) + koff);
                b[nt][0] = bv.x; b[nt][1] = bv.y;
            }
#pragma unroll
            for (int mt = 0; mt < 2; ++mt)
#pragma unroll
                for (int nt = 0; nt < 2; ++nt)
                    mma_bf16(C[mt][nt], a[mt], b[nt]);
        }

        // per-head epilogue (registers only)
        float RjA[4] = {0.f, 0.f, 0.f, 0.f};
#pragma unroll
        for (int mt = 0; mt < 2; ++mt)
#pragma unroll
            for (int nt = 0; nt < 2; ++nt)
#pragma unroll
                for (int k = 0; k < 4; ++k) {
                    const int half = k >> 1, cbit = k & 1;
                    float d = C[mt][nt][k];          // dot*log2e/T + 64  (> 0)
                    float e = ex2f(d);               // exp(dot/T) * 2^64
                    if (diag) {
                        const int rl = 32 * wi + 16 * mt + qt + 8 * half;
                        const int cl = 16 * wj + 8 * nt + 2 * m4 + cbit;
                        if (rl == cl) e = 0.f;
                    }
                    R[mt * 2 + half][h] += e;
                    RjA[nt * 2 + cbit] += e;
                    const int bpi = (mt * 2 + half) * 4 + nt * 2 + cbit;
                    unsigned en = (__float_as_uint(d) & 0xFFFFFFFCu) | (unsigned)h;
                    bp[bpi] = bp[bpi] > en ? bp[bpi] : en;
                }
        if (!diag) {
#pragma unroll
            for (int o = 4; o <= 16; o <<= 1)
#pragma unroll
                for (int c = 0; c < 4; ++c)
                    RjA[c] += __shfl_xor_sync(0xffffffffu, RjA[c], o);
            if (qt == 0) {
#pragma unroll
                for (int c = 0; c < 4; ++c) {
                    int cl = 16 * wj + 8 * (c >> 1) + 2 * m4 + (c & 1);
                    atomicAdd(&sAcc[SRJ + cl * 4 + h], RjA[c]);
                }
            }
        }
    }

    // ---- masked accumulation (row side; plus column side if off-diag) ----
    unsigned bJv[4];
#pragma unroll
    for (int c = 0; c < 4; ++c)
        bJv[c] = sBits[16 * wj + 8 * (c >> 1) + 2 * m4 + (c & 1)];

    float cdot[4]; unsigned cp_[4];
    float cdotj[4] = {0.f, 0.f, 0.f, 0.f};
    unsigned cpj[4] = {0u, 0u, 0u, 0u};

#pragma unroll
    for (int r4 = 0; r4 < 4; ++r4) {
        cdot[r4] = 0.f; cp_[r4] = 0u;
        const unsigned bIr = bI[r4];
        const int rl = 32 * wi + 16 * (r4 >> 1) + qt + 8 * (r4 & 1);
#pragma unroll
        for (int c = 0; c < 4; ++c) {
            bool m = ((bIr & bJv[c]) != 0u);
            if (diag) {
                const int cl = 16 * wj + 8 * (c >> 1) + 2 * m4 + (c & 1);
                if (rl == cl) m = false;
            }
            if (m) {
                unsigned e = bp[r4 * 4 + c];
                float dt = __uint_as_float(e & 0xFFFFFFFCu);   // biased dot
                unsigned inc = 1u << ((e & 3u) * 8);
                cdot[r4] += dt; cp_[r4] += inc;
                cdotj[c] += dt; cpj[c]  += inc;
            }
        }
    }

    // row side: reduce over the 4 m4 lanes, smem-atomic from m4==0
#pragma unroll
    for (int o = 1; o <= 2; o <<= 1) {
#pragma unroll
        for (int r4 = 0; r4 < 4; ++r4) {
            cdot[r4] += __shfl_xor_sync(0xffffffffu, cdot[r4], o);
            cp_[r4]  += __shfl_xor_sync(0xffffffffu, cp_[r4], o);
#pragma unroll
            for (int h = 0; h < 4; ++h)
                R[r4][h] += __shfl_xor_sync(0xffffffffu, R[r4][h], o);
        }
    }
    if (m4 == 0) {
#pragma unroll
        for (int r4 = 0; r4 < 4; ++r4) {
            const int rl = 32 * wi + 16 * (r4 >> 1) + qt + 8 * (r4 & 1);
            atomicAdd(&sAcc[SCDI + rl], cdot[r4]);
#pragma unroll
            for (int h = 0; h < 4; ++h) {
                atomicAdd(&sAcc[SRI + rl * 4 + h], R[r4][h]);
                float cn = (float)((cp_[r4] >> (8 * h)) & 255u);
                if (cn != 0.f) atomicAdd(&sAcc[SCNI + rl * 4 + h], cn);
            }
        }
    }

    // column side (off-diag): reduce over qt lanes, smem-atomic from qt==0
    if (!diag) {
#pragma unroll
        for (int o = 4; o <= 16; o <<= 1)
#pragma unroll
            for (int c = 0; c < 4; ++c) {
                cdotj[c] += __shfl_xor_sync(0xffffffffu, cdotj[c], o);
                cpj[c]   += __shfl_xor_sync(0xffffffffu, cpj[c], o);
            }
        if (qt == 0) {
#pragma unroll
            for (int c = 0; c < 4; ++c) {
                int cl = 16 * wj + 8 * (c >> 1) + 2 * m4 + (c & 1);
                if (cpj[c] != 0u) {
                    atomicAdd(&sAcc[SCDJ + cl], cdotj[c]);
#pragma unroll
                    for (int h = 0; h < 4; ++h) {
                        float cn = (float)((cpj[c] >> (8 * h)) & 255u);
                        if (cn != 0.f) atomicAdd(&sAcc[SCNJ + cl * 4 + h], cn);
                    }
                }
            }
        }
    }

    // ---- single coalesced global flush ----
    __syncthreads();
    if (tid < TILE) {
        const int rl = tid, gi = i0 + rl;
        atomicAdd(&g_dot[gi], sAcc[SCDI + rl]);
#pragma unroll
        for (int h = 0; h < 4; ++h) {
            atomicAdd(&g_R[gi * 4 + h], sAcc[SRI + rl * 4 + h]);
            float cn = sAcc[SCNI + rl * 4 + h];
            if (cn != 0.f) atomicAdd(&g_cnt[gi * 4 + h], cn);
        }
    } else if (!diag && tid < 2 * TILE) {
        const int cl = tid - TILE, gj = j0 + cl;
        atomicAdd(&g_dot[gj], sAcc[SCDJ + cl]);
#pragma unroll
        for (int h = 0; h < 4; ++h) {
            atomicAdd(&g_R[gj * 4 + h], sAcc[SRJ + cl * 4 + h]);
            float cn = sAcc[SCNJ + cl * 4 + h];
            if (cn != 0.f) atomicAdd(&g_cnt[gj * 4 + h], cn);
        }
    }
}

// ---------------- finalize ----------------
// sum_mask log_prob = ln2 * ( sum d_biased - sum_h cnt_h * lg2(R_raw_h) )  (64*ct cancels)
__global__ void finalK(float* __restrict__ out) {
    __shared__ float ss[512], sc[512];
    int tid = threadIdx.x;
    float s = 0.f, c = 0.f;
    for (int i = tid; i < N_; i += 512) {
        float ct = 0.f;
        float acc = g_dot[i];
#pragma unroll
        for (int h = 0; h < 4; ++h) {
            float cn = g_cnt[i * 4 + h];
            ct  += cn;
            acc -= cn * lg2f(g_R[i * 4 + h]);
        }
        float loss = -0.6931471805599453f * acc / ct;   // NaN when ct==0, as in reference
        if (isfinite(loss)) { s += loss; c += 1.f; }
    }
    ss[tid] = s; sc[tid] = c;
    __syncthreads();
    for (int o = 256; o; o >>= 1) {
        if (tid < o) { ss[tid] += ss[tid + o]; sc[tid] += sc[tid + o]; }
        __syncthreads();
    }
    if (tid == 0) out[0] = ss[0] / sc[0];
}

// ---------------- launch ----------------
extern "C" void kernel_launch(void* const* d_in, const int* in_sizes, int n_in,
                              void* d_out, int out_size) {
    const float* features = (const float*)d_in[0];
    const float* labels   = (const float*)d_in[1];
    float* out = (float*)d_out;

    cudaFuncSetAttribute(mainK, cudaFuncAttributeMaxDynamicSharedMemorySize, SMEM_TOTAL);

    preK<<<N_ / 4, 256>>>(features, labels);
    mainK<<<NCTA, THREADS, SMEM_TOTAL>>>();
    finalK<<<1, 512>>>(out);
}